// round 4
// baseline (speedup 1.0000x reference)
#include <cuda_runtime.h>
#include <cstdint>
#include <cstddef>

namespace {
constexpr int kM = 64;
constexpr int kK = 4096;
constexpr int kN = 14336;
constexpr int kBN = 32;               // tile width
constexpr int kBK = 128;              // one quant group
constexpr int kSplit = 2;             // K-split for tail balance
constexpr int kKper = kK / kSplit;    // 2048
constexpr int kChunks = kKper / kBK;  // 16
constexpr int kTiles = kN / kBN;      // 448 -> grid 896
constexpr int kStages = 3;
constexpr int kPad = 144;             // smem row stride (conflict-free ldmatrix)
constexpr int kAStage = 64 * kPad;    // 9216 B
constexpr int kBStage = 32 * kPad;    // 4608 B
}

// device-global scratch (no allocations allowed)
__device__ __align__(16) int8_t g_x8[kM * kK];              // packed int8 activations
__device__ __align__(16) int g_part[kSplit][kM * kN];       // int32 split partials

__global__ void pack_x_kernel(const int* __restrict__ x) {
    int idx = blockIdx.x * blockDim.x + threadIdx.x;  // int4 index over M*K/4
    int4 v = __ldg(((const int4*)x) + idx);
    uint32_t w = (uint32_t)(v.x & 0xff) | ((uint32_t)(v.y & 0xff) << 8)
               | ((uint32_t)(v.z & 0xff) << 16) | ((uint32_t)(v.w & 0xff) << 24);
    ((uint32_t*)g_x8)[idx] = w;
}

// ---------------- PTX helpers (all baseline sm_80+/sm_90 features) ------------
__device__ __forceinline__ uint32_t smem_u32(const void* p) {
    return (uint32_t)__cvta_generic_to_shared(p);
}
__device__ __forceinline__ void cp_async16(uint32_t dst, const void* src) {
    asm volatile("cp.async.ca.shared.global [%0], [%1], 16;\n" :: "r"(dst), "l"(src));
}
__device__ __forceinline__ void cp_async_mbar_arrive(uint32_t bar) {
    asm volatile("cp.async.mbarrier.arrive.noinc.shared::cta.b64 [%0];" :: "r"(bar) : "memory");
}
__device__ __forceinline__ void mbar_init(uint32_t addr, uint32_t cnt) {
    asm volatile("mbarrier.init.shared.b64 [%0], %1;" :: "r"(addr), "r"(cnt) : "memory");
}
__device__ __forceinline__ void mbar_arrive(uint32_t addr) {
    asm volatile("mbarrier.arrive.release.cta.shared::cta.b64 _, [%0];" :: "r"(addr) : "memory");
}
__device__ __forceinline__ void mbar_wait(uint32_t addr, uint32_t parity) {
    uint32_t done;
    asm volatile("{\n\t.reg .pred p;\n\t"
                 "mbarrier.try_wait.parity.acquire.cta.shared::cta.b64 p, [%1], %2;\n\t"
                 "selp.b32 %0, 1, 0, p;\n\t}"
                 : "=r"(done) : "r"(addr), "r"(parity) : "memory");
    if (!done) {
        asm volatile("{\n\t.reg .pred P1;\n\t"
                     "WL_%=:\n\t"
                     "mbarrier.try_wait.parity.acquire.cta.shared::cta.b64 P1, [%0], %1, 0x989680;\n\t"
                     "@P1 bra.uni WD_%=;\n\t"
                     "bra.uni WL_%=;\n\t"
                     "WD_%=:\n\t}" :: "r"(addr), "r"(parity) : "memory");
    }
}
__device__ __forceinline__ void ldmatrix_x4(uint32_t r[4], uint32_t addr) {
    asm volatile("ldmatrix.sync.aligned.m8n8.x4.shared.b16 {%0,%1,%2,%3}, [%4];"
                 : "=r"(r[0]), "=r"(r[1]), "=r"(r[2]), "=r"(r[3]) : "r"(addr));
}
__device__ __forceinline__ void mma_s8(int c[4], uint32_t a0, uint32_t a1, uint32_t a2,
                                       uint32_t a3, uint32_t b0, uint32_t b1) {
    asm volatile(
        "mma.sync.aligned.m16n8k32.row.col.s32.s8.s8.s32 "
        "{%0,%1,%2,%3}, {%4,%5,%6,%7}, {%8,%9}, {%0,%1,%2,%3};\n"
        : "+r"(c[0]), "+r"(c[1]), "+r"(c[2]), "+r"(c[3])
        : "r"(a0), "r"(a1), "r"(a2), "r"(a3), "r"(b0), "r"(b1));
}

// ---------------- warp-specialized GEMM ----------------
__global__ void __launch_bounds__(256)
w4a8_gemm(const int* __restrict__ qweight,
          const int* __restrict__ s2_scales,
          const int* __restrict__ s2_zeros) {
    __shared__ __align__(16) int8_t As[kStages][kAStage];
    __shared__ __align__(16) int8_t Bs[kStages][kBStage];
    __shared__ __align__(8) uint64_t barf[kStages];  // full
    __shared__ __align__(8) uint64_t bare[kStages];  // empty

    const int tid = threadIdx.x;
    const int bid = blockIdx.x;
    const int split = bid & 1;
    const int tile = bid >> 1;
    const int n0 = tile * kBN;
    const int k0 = split * kKper;   // k offset in int32 elements

    uint32_t full[kStages], empt[kStages];
#pragma unroll
    for (int s = 0; s < kStages; ++s) {
        full[s] = smem_u32(&barf[s]);
        empt[s] = smem_u32(&bare[s]);
    }
    if (tid < kStages) {
        mbar_init(full[tid], 256);  // 128 STS arrivals + 128 cp.async arrivals
        mbar_init(empt[tid], 128);  // 128 consumer threads
    }
    __syncthreads();

    if (tid < 128) {
        // ================= producers: 4 warps =================
        const int nl = tid >> 2;   // 0..31 weight row within tile
        const int qtr = tid & 3;   // quarter of the 128B chunk row
        const int n_glob = n0 + nl;
        // k0 is int32 elements -> k0/4 int4 units  (R3 bug was k0/16)
        const int4* qrow = (const int4*)qweight + (size_t)n_glob * (kK / 4) + (k0 / 4);
        const int grp0 = k0 / kBK;

        for (int c = 0; c < kChunks; ++c) {
            const int s = c % kStages, lap = c / kStages;

            // issue globals first (MLP across the empty-wait)
            int4 qv[8];
#pragma unroll
            for (int j = 0; j < 8; ++j)
                qv[j] = __ldcs(qrow + c * 32 + qtr * 8 + j);
            const int s2 = __ldg(s2_scales + (grp0 + c) * kN + n_glob);
            const int zz = __ldg(s2_zeros + (grp0 + c) * kN + n_glob);

            if (c >= kStages) mbar_wait(empt[s], (lap - 1) & 1);

            // A tile (64 x 128 int8) via cp.async, 4 x 16B per thread
#pragma unroll
            for (int j = 0; j < 4; ++j) {
                int id = tid + 128 * j;
                int row = id >> 3, seg = id & 7;
                cp_async16(smem_u32(&As[s][row * kPad + seg * 16]),
                           g_x8 + (size_t)row * kK + k0 + c * kBK + seg * 16);
            }
            cp_async_mbar_arrive(full[s]);

            // dequant w = q*s2 + z (exact int8) and STS
            uint32_t w[8];
#pragma unroll
            for (int j = 0; j < 8; ++j) {
                int b0 = qv[j].x * s2 + zz;
                int b1 = qv[j].y * s2 + zz;
                int b2 = qv[j].z * s2 + zz;
                int b3 = qv[j].w * s2 + zz;
                w[j] = (uint32_t)(b0 & 0xff) | ((uint32_t)(b1 & 0xff) << 8)
                     | ((uint32_t)(b2 & 0xff) << 16) | ((uint32_t)b3 << 24);
            }
            int8_t* brow = &Bs[s][nl * kPad + qtr * 32];
            *(uint4*)brow = make_uint4(w[0], w[1], w[2], w[3]);
            *(uint4*)(brow + 16) = make_uint4(w[4], w[5], w[6], w[7]);
            mbar_arrive(full[s]);
        }
    } else {
        // ================= consumers: 4 warps, mma only =================
        const int ct = tid - 128;
        const int cw = ct >> 5;      // m-tile 0..3
        const int lane = ct & 31;
        // ldmatrix address components (A: m16k32 as 4 8x8 b16 matrices)
        const int arow = cw * 16 + (lane & 7) + ((lane >> 3) & 1) * 8;
        const int ahalf = ((lane >> 4) & 1) * 16;
        // B: x4 covers one 16-wide n-group; matrices = {n0-7,k0-15},{n0-7,k16-31},
        //                                              {n8-15,k0-15},{n8-15,k16-31}
        const int bmat = lane >> 3;
        const int brow_pair = (bmat >> 1) * 8 + (lane & 7);
        const int bkhalf = (bmat & 1) * 16;

        int acc[4][4] = {};
        for (int c = 0; c < kChunks; ++c) {
            const int s = c % kStages, lap = c / kStages;
            mbar_wait(full[s], lap & 1);
#pragma unroll
            for (int ks = 0; ks < 4; ++ks) {
                uint32_t a[4];
                ldmatrix_x4(a, smem_u32(&As[s][arow * kPad + ks * 32 + ahalf]));
                uint32_t b[2][4];
#pragma unroll
                for (int p = 0; p < 2; ++p)
                    ldmatrix_x4(b[p],
                        smem_u32(&Bs[s][(p * 16 + brow_pair) * kPad + ks * 32 + bkhalf]));
#pragma unroll
                for (int i = 0; i < 4; ++i)
                    mma_s8(acc[i], a[0], a[1], a[2], a[3],
                           b[i >> 1][(i & 1) * 2], b[i >> 1][(i & 1) * 2 + 1]);
            }
            mbar_arrive(empt[s]);
        }

        // store int32 partials to this split's slice
        const int r0 = cw * 16 + (lane >> 2);
        int* pbase = &g_part[split][0];
#pragma unroll
        for (int i = 0; i < 4; ++i) {
            int n = n0 + i * 8 + 2 * (lane & 3);
            *(int2*)(pbase + (size_t)r0 * kN + n) = make_int2(acc[i][0], acc[i][1]);
            *(int2*)(pbase + (size_t)(r0 + 8) * kN + n) = make_int2(acc[i][2], acc[i][3]);
        }
    }
}

// ---------------- epilogue: sum splits, scale, bias ----------------
__global__ void epilogue_kernel(const float* __restrict__ input_scales,
                                const float* __restrict__ s1_scales,
                                const float* __restrict__ bias,
                                float* __restrict__ out) {
    int idx = blockIdx.x * blockDim.x + threadIdx.x;  // quad index over M*N/4
    int m = idx / (kN / 4);
    int n = (idx - m * (kN / 4)) * 4;
    int4 p0 = *(const int4*)&g_part[0][(size_t)m * kN + n];
    int4 p1 = *(const int4*)&g_part[1][(size_t)m * kN + n];
    float is = input_scales[m];
    float4 s = *(const float4*)(s1_scales + n);
    float4 b = *(const float4*)(bias + n);
    float4 o;
    o.x = (float)(p0.x + p1.x) * is * s.x + b.x;
    o.y = (float)(p0.y + p1.y) * is * s.y + b.y;
    o.z = (float)(p0.z + p1.z) * is * s.z + b.z;
    o.w = (float)(p0.w + p1.w) * is * s.w + b.w;
    *(float4*)(out + (size_t)m * kN + n) = o;
}

extern "C" void kernel_launch(void* const* d_in, const int* in_sizes, int n_in,
                              void* d_out, int out_size) {
    const int* x           = (const int*)d_in[0];
    const float* in_scales = (const float*)d_in[1];
    // d_in[2] = input_sum (unused)
    const int* qweight     = (const int*)d_in[3];
    const int* s2_scales   = (const int*)d_in[4];
    const int* s2_zeros    = (const int*)d_in[5];
    const float* s1_scales = (const float*)d_in[6];
    const float* bias      = (const float*)d_in[7];
    float* out             = (float*)d_out;
    (void)in_sizes; (void)n_in; (void)out_size;

    pack_x_kernel<<<(kM * kK / 4) / 256, 256>>>(x);
    w4a8_gemm<<<kTiles * kSplit, 256>>>(qweight, s2_scales, s2_zeros);
    epilogue_kernel<<<(kM * kN / 4) / 256, 256>>>(in_scales, s1_scales, bias, out);
}

// round 5
// speedup vs baseline: 1.2709x; 1.2709x over previous
#include <cuda_runtime.h>
#include <cstdint>
#include <cstddef>

namespace {
constexpr int kM = 64;
constexpr int kK = 4096;
constexpr int kN = 14336;
constexpr int kBN = 16;               // tile width -> grid 896, fine-grain tail
constexpr int kBK = 128;              // one quant group per chunk
constexpr int kChunks = kK / kBK;     // 32
constexpr int kPad = 144;             // smem row stride (conflict-free ldmatrix)
constexpr int kAStage = 64 * kPad;    // 9216 B
constexpr int kBStage = kBN * kPad;   // 2304 B
constexpr int kThreads = 256;
}

// device-global scratch (no allocations allowed)
__device__ __align__(16) int8_t g_x8[kM * kK];  // packed int8 activations

__global__ void pack_x_kernel(const int* __restrict__ x) {
    int idx = blockIdx.x * blockDim.x + threadIdx.x;  // int4 index over M*K/4
    int4 v = __ldg(((const int4*)x) + idx);
    uint32_t w = (uint32_t)(v.x & 0xff) | ((uint32_t)(v.y & 0xff) << 8)
               | ((uint32_t)(v.z & 0xff) << 16) | ((uint32_t)(v.w & 0xff) << 24);
    ((uint32_t*)g_x8)[idx] = w;
}

// ---------------- PTX helpers ----------------
__device__ __forceinline__ uint32_t smem_u32(const void* p) {
    return (uint32_t)__cvta_generic_to_shared(p);
}
__device__ __forceinline__ void cp_async16(uint32_t dst, const void* src) {
    asm volatile("cp.async.ca.shared.global [%0], [%1], 16;\n" :: "r"(dst), "l"(src));
}
__device__ __forceinline__ void cp_commit() { asm volatile("cp.async.commit_group;\n"); }
__device__ __forceinline__ void cp_wait_all() { asm volatile("cp.async.wait_group 0;\n" ::: "memory"); }
__device__ __forceinline__ uint32_t prmt(uint32_t a, uint32_t b, uint32_t sel) {
    uint32_t d;
    asm("prmt.b32 %0, %1, %2, %3;" : "=r"(d) : "r"(a), "r"(b), "r"(sel));
    return d;
}
__device__ __forceinline__ void ldmatrix_x4(uint32_t r[4], uint32_t addr) {
    asm volatile("ldmatrix.sync.aligned.m8n8.x4.shared.b16 {%0,%1,%2,%3}, [%4];"
                 : "=r"(r[0]), "=r"(r[1]), "=r"(r[2]), "=r"(r[3]) : "r"(addr));
}
__device__ __forceinline__ void mma_s8(int c[4], uint32_t a0, uint32_t a1, uint32_t a2,
                                       uint32_t a3, uint32_t b0, uint32_t b1) {
    asm volatile(
        "mma.sync.aligned.m16n8k32.row.col.s32.s8.s8.s32 "
        "{%0,%1,%2,%3}, {%4,%5,%6,%7}, {%8,%9}, {%0,%1,%2,%3};\n"
        : "+r"(c[0]), "+r"(c[1]), "+r"(c[2]), "+r"(c[3])
        : "r"(a0), "r"(a1), "r"(a2), "r"(a3), "r"(b0), "r"(b1));
}

// ---------------- cooperative GEMM (R1 structure, BN=16, ldmatrix) ----------------
__global__ void __launch_bounds__(kThreads)
w4a8_gemm(const int* __restrict__ qweight,
          const int* __restrict__ s2_scales,
          const int* __restrict__ s2_zeros,
          const float* __restrict__ input_scales,
          const float* __restrict__ s1_scales,
          const float* __restrict__ bias,
          float* __restrict__ out) {
    __shared__ __align__(16) int8_t As[2][kAStage];
    __shared__ __align__(16) int8_t Bs[2][kBStage];

    const int tid = threadIdx.x;
    const int warp = tid >> 5;
    const int lane = tid & 31;
    const int n0 = blockIdx.x * kBN;

    // ---- producer mapping: 16 rows x 16 segments (8 values each) ----
    const int nl = tid >> 4;           // 0..15 weight row in tile
    const int seg = tid & 15;          // 8-value segment within the 128-wide chunk
    const int n_glob = n0 + nl;
    const int4* qrow = (const int4*)qweight + (size_t)n_glob * (kK / 4);

    int4 qv0, qv1;
    int s2r, zr;

    auto ldg_chunk = [&](int c) {
        qv0 = __ldcs(qrow + c * 32 + seg * 2);
        qv1 = __ldcs(qrow + c * 32 + seg * 2 + 1);
        s2r = __ldg(s2_scales + c * kN + n_glob);
        zr  = __ldg(s2_zeros + c * kN + n_glob);
    };
    auto cp_a = [&](int c, int s) {
#pragma unroll
        for (int j = 0; j < 2; ++j) {
            int id = tid + kThreads * j;           // 0..511
            int row = id >> 3, sg = id & 7;
            cp_async16(smem_u32(&As[s][row * kPad + sg * 16]),
                       g_x8 + (size_t)row * kK + c * kBK + sg * 16);
        }
        cp_commit();
    };
    auto dequant_sts = [&](int s) {
        // w = q*s2 + z, exact int8 (|w| <= 105); byte0 of each IMAD result
        int b0 = qv0.x * s2r + zr, b1 = qv0.y * s2r + zr;
        int b2 = qv0.z * s2r + zr, b3 = qv0.w * s2r + zr;
        uint32_t p01 = prmt((uint32_t)b0, (uint32_t)b1, 0x0040);
        uint32_t p23 = prmt((uint32_t)b2, (uint32_t)b3, 0x0040);
        uint32_t pk0 = prmt(p01, p23, 0x5410);
        int c0 = qv1.x * s2r + zr, c1 = qv1.y * s2r + zr;
        int c2 = qv1.z * s2r + zr, c3 = qv1.w * s2r + zr;
        uint32_t q01 = prmt((uint32_t)c0, (uint32_t)c1, 0x0040);
        uint32_t q23 = prmt((uint32_t)c2, (uint32_t)c3, 0x0040);
        uint32_t pk1 = prmt(q01, q23, 0x5410);
        *(uint2*)(&Bs[s][nl * kPad + seg * 8]) = make_uint2(pk0, pk1);
    };

    // ---- consumer mapping (validated in R4): warp -> (m-tile, n-tile) ----
    const int mt = warp & 3;       // 16-row m-tile
    const int nt = warp >> 2;      // 8-col n-tile
    const uint32_t a_off = (uint32_t)((mt * 16 + (lane & 7) + ((lane >> 3) & 1) * 8) * kPad
                                      + ((lane >> 4) & 1) * 16);
    const uint32_t b_off = (uint32_t)((nt * 8 + (lane & 7)) * kPad + (lane >> 3) * 16);
    int acc[4] = {};

    // ---- prologue: chunk 0 into buffer 0 ----
    ldg_chunk(0);
    cp_a(0, 0);
    dequant_sts(0);
    cp_wait_all();
    __syncthreads();

    for (int c = 0; c < kChunks; ++c) {
        const int s = c & 1;
        if (c + 1 < kChunks) {
            ldg_chunk(c + 1);      // issue globals early (hidden behind mma)
            cp_a(c + 1, s ^ 1);
        }

        const uint32_t abase = smem_u32(&As[s][0]) + a_off;
        const uint32_t bbase = smem_u32(&Bs[s][0]) + b_off;
#pragma unroll
        for (int kp = 0; kp < 2; ++kp) {
            uint32_t b[4];
            ldmatrix_x4(b, bbase + kp * 64);
#pragma unroll
            for (int k2 = 0; k2 < 2; ++k2) {
                uint32_t a[4];
                ldmatrix_x4(a, abase + (kp * 2 + k2) * 32);
                mma_s8(acc, a[0], a[1], a[2], a[3], b[k2 * 2], b[k2 * 2 + 1]);
            }
        }

        if (c + 1 < kChunks) dequant_sts(s ^ 1);
        cp_wait_all();
        __syncthreads();
    }

    // ---- fused epilogue ----
    const int r = mt * 16 + (lane >> 2);
    const int n = n0 + nt * 8 + (lane & 3) * 2;
    const float is0 = input_scales[r];
    const float is1 = input_scales[r + 8];
    const float s1a = s1_scales[n], s1b = s1_scales[n + 1];
    const float ba = bias[n], bb = bias[n + 1];
    *(float2*)(out + (size_t)r * kN + n) =
        make_float2((float)acc[0] * is0 * s1a + ba, (float)acc[1] * is0 * s1b + bb);
    *(float2*)(out + (size_t)(r + 8) * kN + n) =
        make_float2((float)acc[2] * is1 * s1a + ba, (float)acc[3] * is1 * s1b + bb);
}

extern "C" void kernel_launch(void* const* d_in, const int* in_sizes, int n_in,
                              void* d_out, int out_size) {
    const int* x           = (const int*)d_in[0];
    const float* in_scales = (const float*)d_in[1];
    // d_in[2] = input_sum (unused)
    const int* qweight     = (const int*)d_in[3];
    const int* s2_scales   = (const int*)d_in[4];
    const int* s2_zeros    = (const int*)d_in[5];
    const float* s1_scales = (const float*)d_in[6];
    const float* bias      = (const float*)d_in[7];
    float* out             = (float*)d_out;
    (void)in_sizes; (void)n_in; (void)out_size;

    pack_x_kernel<<<(kM * kK / 4) / kThreads, kThreads>>>(x);
    w4a8_gemm<<<kN / kBN, kThreads>>>(qweight, s2_scales, s2_zeros,
                                      in_scales, s1_scales, bias, out);
}

// round 6
// speedup vs baseline: 1.3008x; 1.0235x over previous
#include <cuda_runtime.h>
#include <cstdint>
#include <cstddef>

namespace {
constexpr int kM = 64;
constexpr int kK = 4096;
constexpr int kN = 14336;
constexpr int kBN = 16;               // tile width -> grid 896, fine-grain tail
constexpr int kBK = 128;              // one quant group per chunk
constexpr int kChunks = kK / kBK;     // 32
constexpr int kPad = 144;             // smem row stride (conflict-free ldmatrix)
constexpr int kAStage = 64 * kPad;    // 9216 B
constexpr int kBStage = kBN * kPad;   // 2304 B
constexpr int kThreads = 256;
}

// device-global scratch (no allocations allowed)
__device__ __align__(16) int8_t g_x8[kM * kK];  // packed int8 activations

__global__ void pack_x_kernel(const int* __restrict__ x) {
    int idx = blockIdx.x * blockDim.x + threadIdx.x;  // int4 index over M*K/4
    int4 v = __ldg(((const int4*)x) + idx);
    uint32_t w = (uint32_t)(v.x & 0xff) | ((uint32_t)(v.y & 0xff) << 8)
               | ((uint32_t)(v.z & 0xff) << 16) | ((uint32_t)(v.w & 0xff) << 24);
    ((uint32_t*)g_x8)[idx] = w;
}

// ---------------- PTX helpers ----------------
__device__ __forceinline__ uint32_t smem_u32(const void* p) {
    return (uint32_t)__cvta_generic_to_shared(p);
}
__device__ __forceinline__ void cp_async16(uint32_t dst, const void* src) {
    asm volatile("cp.async.ca.shared.global [%0], [%1], 16;\n" :: "r"(dst), "l"(src));
}
__device__ __forceinline__ void cp_commit() { asm volatile("cp.async.commit_group;\n"); }
__device__ __forceinline__ void cp_wait_all() { asm volatile("cp.async.wait_group 0;\n" ::: "memory"); }
__device__ __forceinline__ uint32_t prmt(uint32_t a, uint32_t b, uint32_t sel) {
    uint32_t d;
    asm("prmt.b32 %0, %1, %2, %3;" : "=r"(d) : "r"(a), "r"(b), "r"(sel));
    return d;
}
__device__ __forceinline__ void ldmatrix_x4(uint32_t r[4], uint32_t addr) {
    asm volatile("ldmatrix.sync.aligned.m8n8.x4.shared.b16 {%0,%1,%2,%3}, [%4];"
                 : "=r"(r[0]), "=r"(r[1]), "=r"(r[2]), "=r"(r[3]) : "r"(addr));
}
__device__ __forceinline__ void mma_s8(int c[4], uint32_t a0, uint32_t a1, uint32_t a2,
                                       uint32_t a3, uint32_t b0, uint32_t b1) {
    asm volatile(
        "mma.sync.aligned.m16n8k32.row.col.s32.s8.s8.s32 "
        "{%0,%1,%2,%3}, {%4,%5,%6,%7}, {%8,%9}, {%0,%1,%2,%3};\n"
        : "+r"(c[0]), "+r"(c[1]), "+r"(c[2]), "+r"(c[3])
        : "r"(a0), "r"(a1), "r"(a2), "r"(a3), "r"(b0), "r"(b1));
}

// ---------------- cooperative GEMM: BN=16, depth-2 q prefetch, split acc chains
__global__ void __launch_bounds__(kThreads, 4)
w4a8_gemm(const int* __restrict__ qweight,
          const int* __restrict__ s2_scales,
          const int* __restrict__ s2_zeros,
          const float* __restrict__ input_scales,
          const float* __restrict__ s1_scales,
          const float* __restrict__ bias,
          float* __restrict__ out) {
    __shared__ __align__(16) int8_t As[2][kAStage];
    __shared__ __align__(16) int8_t Bs[2][kBStage];

    const int tid = threadIdx.x;
    const int warp = tid >> 5;
    const int lane = tid & 31;
    const int n0 = blockIdx.x * kBN;

    // ---- producer mapping: 16 rows x 16 segments (8 values each) ----
    const int nl = tid >> 4;           // 0..15 weight row in tile
    const int seg = tid & 15;          // 8-value segment within the 128-wide chunk
    const int n_glob = n0 + nl;
    const int4* qrow = (const int4*)qweight + (size_t)n_glob * (kK / 4);

    // depth-2 register prefetch: chunk j lives in slot j&1
    int4 qv0[2], qv1[2];
    int s2r[2], zr[2];

    auto ldg_chunk = [&](int c) {
        const int b = c & 1;
        qv0[b] = __ldcs(qrow + c * 32 + seg * 2);
        qv1[b] = __ldcs(qrow + c * 32 + seg * 2 + 1);
        s2r[b] = __ldg(s2_scales + c * kN + n_glob);
        zr[b]  = __ldg(s2_zeros + c * kN + n_glob);
    };
    auto cp_a = [&](int c, int s) {
#pragma unroll
        for (int j = 0; j < 2; ++j) {
            int id = tid + kThreads * j;           // 0..511
            int row = id >> 3, sg = id & 7;
            cp_async16(smem_u32(&As[s][row * kPad + sg * 16]),
                       g_x8 + (size_t)row * kK + c * kBK + sg * 16);
        }
        cp_commit();
    };
    auto dequant_sts = [&](int c, int s) {
        const int b = c & 1;
        const int sc = s2r[b], zc = zr[b];
        int b0 = qv0[b].x * sc + zc, b1 = qv0[b].y * sc + zc;
        int b2 = qv0[b].z * sc + zc, b3 = qv0[b].w * sc + zc;
        uint32_t p01 = prmt((uint32_t)b0, (uint32_t)b1, 0x0040);
        uint32_t p23 = prmt((uint32_t)b2, (uint32_t)b3, 0x0040);
        uint32_t pk0 = prmt(p01, p23, 0x5410);
        int c0 = qv1[b].x * sc + zc, c1 = qv1[b].y * sc + zc;
        int c2 = qv1[b].z * sc + zc, c3 = qv1[b].w * sc + zc;
        uint32_t q01 = prmt((uint32_t)c0, (uint32_t)c1, 0x0040);
        uint32_t q23 = prmt((uint32_t)c2, (uint32_t)c3, 0x0040);
        uint32_t pk1 = prmt(q01, q23, 0x5410);
        *(uint2*)(&Bs[s][nl * kPad + seg * 8]) = make_uint2(pk0, pk1);
    };

    // ---- consumer mapping (validated): warp -> (m-tile, n-tile) ----
    const int mt = warp & 3;       // 16-row m-tile
    const int nt = warp >> 2;      // 8-col n-tile
    const uint32_t a_off = (uint32_t)((mt * 16 + (lane & 7) + ((lane >> 3) & 1) * 8) * kPad
                                      + ((lane >> 4) & 1) * 16);
    const uint32_t b_off = (uint32_t)((nt * 8 + (lane & 7)) * kPad + (lane >> 3) * 16);
    int acc[2][4] = {};   // two independent chains (k-halves of each chunk)

    // ---- prologue: chunks 0 and 1 into register slots; stage 0 built ----
    ldg_chunk(0);
    ldg_chunk(1);
    cp_a(0, 0);
    dequant_sts(0, 0);
    cp_wait_all();
    __syncthreads();

    for (int c = 0; c < kChunks; ++c) {
        const int s = c & 1;
        if (c + 2 < kChunks) ldg_chunk(c + 2);   // slot (c&1): chunk c already consumed
        if (c + 1 < kChunks) cp_a(c + 1, s ^ 1);

        const uint32_t abase = smem_u32(&As[s][0]) + a_off;
        const uint32_t bbase = smem_u32(&Bs[s][0]) + b_off;
#pragma unroll
        for (int kp = 0; kp < 2; ++kp) {
            uint32_t b[4];
            ldmatrix_x4(b, bbase + kp * 64);
#pragma unroll
            for (int k2 = 0; k2 < 2; ++k2) {
                uint32_t a[4];
                ldmatrix_x4(a, abase + (kp * 2 + k2) * 32);
                mma_s8(acc[kp], a[0], a[1], a[2], a[3], b[k2 * 2], b[k2 * 2 + 1]);
            }
        }

        if (c + 1 < kChunks) dequant_sts(c + 1, s ^ 1);
        cp_wait_all();
        __syncthreads();
    }

    // ---- fused epilogue (merge the two chains) ----
    const int r = mt * 16 + (lane >> 2);
    const int n = n0 + nt * 8 + (lane & 3) * 2;
    const float is0 = input_scales[r];
    const float is1 = input_scales[r + 8];
    const float s1a = s1_scales[n], s1b = s1_scales[n + 1];
    const float ba = bias[n], bb = bias[n + 1];
    const int a0 = acc[0][0] + acc[1][0], a1 = acc[0][1] + acc[1][1];
    const int a2 = acc[0][2] + acc[1][2], a3 = acc[0][3] + acc[1][3];
    *(float2*)(out + (size_t)r * kN + n) =
        make_float2((float)a0 * is0 * s1a + ba, (float)a1 * is0 * s1b + bb);
    *(float2*)(out + (size_t)(r + 8) * kN + n) =
        make_float2((float)a2 * is1 * s1a + ba, (float)a3 * is1 * s1b + bb);
}

extern "C" void kernel_launch(void* const* d_in, const int* in_sizes, int n_in,
                              void* d_out, int out_size) {
    const int* x           = (const int*)d_in[0];
    const float* in_scales = (const float*)d_in[1];
    // d_in[2] = input_sum (unused)
    const int* qweight     = (const int*)d_in[3];
    const int* s2_scales   = (const int*)d_in[4];
    const int* s2_zeros    = (const int*)d_in[5];
    const float* s1_scales = (const float*)d_in[6];
    const float* bias      = (const float*)d_in[7];
    float* out             = (float*)d_out;
    (void)in_sizes; (void)n_in; (void)out_size;

    pack_x_kernel<<<(kM * kK / 4) / kThreads, kThreads>>>(x);
    w4a8_gemm<<<kN / kBN, kThreads>>>(qweight, s2_scales, s2_zeros,
                                      in_scales, s1_scales, bias, out);
}